// round 14
// baseline (speedup 1.0000x reference)
#include <cuda_runtime.h>
#include <cuda_bf16.h>
#include <cuda_fp8.h>
#include <cuda_fp16.h>
#include <math.h>

// Problem constants
#define NQ      6400
#define CDIM    128
#define SCAM    6
#define MPIX    2816     // 32*88
#define HEADS   4
#define POINTS  20
#define HSZ     32
#define WSZ     88
#define DHEAD   32
#define DANCH   4
#define OFF_W   160      // HEADS*POINTS*2
#define ATTN_W  80       // HEADS*POINTS
#define NCOMB   240      // OFF_W + ATTN_W

#define TM      64       // rows per GEMM block
#define ACOLS   80       // columns per kernel-A part

// Padded value image: x in [-1, 89] (91 cols), y in [-1, 33] (35 rows).
// Borders never written; device globals zero-initialized -> zero padding.
#define PADW    91
#define PADH    35
#define IMGSZ   (PADH * PADW * CDIM)

// Scratch (device globals -- no allocation allowed)
__device__ float         g_off[NQ * OFF_W];
__device__ float         g_aw [NQ * ATTN_W];
__device__ unsigned char g_val[SCAM * IMGSZ];            // padded fp8 e4m3 value image
__device__ float         g_slots[NQ * CDIM];

// Aux stream for A||B overlap -- created once in a static initializer.
namespace {
struct AuxStream {
    cudaStream_t s;
    cudaEvent_t evFork, evJoin;
    AuxStream() {
        cudaStreamCreateWithFlags(&s, cudaStreamNonBlocking);
        cudaEventCreateWithFlags(&evFork, cudaEventDisableTiming);
        cudaEventCreateWithFlags(&evJoin, cudaEventDisableTiming);
    }
};
AuxStream g_aux;
}

// ---------------------------------------------------------------------------
// Kernel A (unchanged, 3-way col-split)
// ---------------------------------------------------------------------------
__global__ void k_proj_off_attn_t(const float* __restrict__ query,
                                  const float* __restrict__ qpos,
                                  const float* __restrict__ Woff,
                                  const float* __restrict__ boff,
                                  const float* __restrict__ Wattn,
                                  const float* __restrict__ battn) {
    extern __shared__ float smem[];
    float* sW = smem;                 // [128][80]
    float* sA = smem + 128 * ACOLS;   // [64][128]

    const int bx   = blockIdx.x;
    const int n0   = (bx / 3) * TM;
    const int part = bx % 3;
    const int tid  = threadIdx.x;

    if (part < 2) {
        for (int idx = tid; idx < 128 * 20; idx += 256) {
            const int k = idx / 20, c4 = idx % 20;
            reinterpret_cast<float4*>(sW)[idx] =
                *reinterpret_cast<const float4*>(&Woff[k * OFF_W + part * ACOLS + c4 * 4]);
        }
    } else {
        for (int idx = tid; idx < 128 * 20; idx += 256)
            reinterpret_cast<float4*>(sW)[idx] = reinterpret_cast<const float4*>(Wattn)[idx];
    }
    for (int idx = tid; idx < TM * 128 / 4; idx += 256) {
        const float4 q4 = reinterpret_cast<const float4*>(query + (size_t)n0 * CDIM)[idx];
        const float4 p4 = reinterpret_cast<const float4*>(qpos + (size_t)n0 * CDIM)[idx];
        reinterpret_cast<float4*>(sA)[idx] =
            make_float4(q4.x + p4.x, q4.y + p4.y, q4.z + p4.z, q4.w + p4.w);
    }
    __syncthreads();

    const int ty = tid >> 4;
    const int tx = tid & 15;

    float acc[4][5];
    #pragma unroll
    for (int i = 0; i < 4; i++)
        #pragma unroll
        for (int j = 0; j < 5; j++) acc[i][j] = 0.f;

    #pragma unroll 4
    for (int k = 0; k < 128; k++) {
        float a[4];
        #pragma unroll
        for (int i = 0; i < 4; i++) a[i] = sA[(ty * 4 + i) * 128 + k];
        #pragma unroll
        for (int j = 0; j < 5; j++) {
            const float w = sW[k * ACOLS + tx + 16 * j];
            #pragma unroll
            for (int i = 0; i < 4; i++) acc[i][j] = fmaf(a[i], w, acc[i][j]);
        }
    }

    if (part < 2) {
        #pragma unroll
        for (int i = 0; i < 4; i++) {
            const int r = n0 + ty * 4 + i;
            #pragma unroll
            for (int j = 0; j < 5; j++) {
                const int c = tx + 16 * j;
                const int t = part * ACOLS + c;
                const float v = acc[i][j] + boff[t];
                g_off[(size_t)r * OFF_W + t] = v * ((t & 1) ? (1.f / 32.f) : (1.f / 88.f));
            }
        }
    } else {
        __syncthreads();
        #pragma unroll
        for (int i = 0; i < 4; i++)
            #pragma unroll
            for (int j = 0; j < 5; j++)
                sW[(ty * 4 + i) * ACOLS + tx + 16 * j] = acc[i][j];
        __syncthreads();

        const int r = tid >> 2, h = tid & 3;
        float lg[POINTS];
        float mx = -1e30f;
        #pragma unroll
        for (int p = 0; p < POINTS; p++) {
            lg[p] = sW[r * ACOLS + h * POINTS + p] + battn[h * POINTS + p];
            mx = fmaxf(mx, lg[p]);
        }
        float sum = 0.f;
        #pragma unroll
        for (int p = 0; p < POINTS; p++) { lg[p] = __expf(lg[p] - mx); sum += lg[p]; }
        const float inv = 1.f / sum;
        #pragma unroll
        for (int p = 0; p < POINTS; p++)
            g_aw[(size_t)(n0 + r) * ATTN_W + h * POINTS + p] = lg[p] * inv;
    }
}

// ---------------------------------------------------------------------------
// Kernel B (unchanged, col-split, padded-image store)
// ---------------------------------------------------------------------------
__global__ void k_proj_val_t(const float* __restrict__ value,
                             const float* __restrict__ Wv,
                             const float* __restrict__ bv) {
    extern __shared__ float smem[];
    float* sW = smem;                 // [128][64]
    float* sA = smem + 128 * 64;      // [64][128]

    const int bx  = blockIdx.x;
    const int r0  = (bx >> 1) * TM;
    const int ch  = (bx & 1) * 64;
    const int tid = threadIdx.x;

    for (int idx = tid; idx < 128 * 16; idx += 256) {
        const int k = idx >> 4, c4 = idx & 15;
        reinterpret_cast<float4*>(sW)[idx] =
            *reinterpret_cast<const float4*>(&Wv[k * 128 + ch + c4 * 4]);
    }
    for (int idx = tid; idx < TM * 128 / 4; idx += 256)
        reinterpret_cast<float4*>(sA)[idx] =
            reinterpret_cast<const float4*>(value + (size_t)r0 * CDIM)[idx];
    __syncthreads();

    const int ty = tid >> 4;
    const int tx = tid & 15;

    float acc[4][4];
    #pragma unroll
    for (int i = 0; i < 4; i++)
        #pragma unroll
        for (int j = 0; j < 4; j++) acc[i][j] = 0.f;

    for (int k4 = 0; k4 < 128; k4 += 4) {
        float4 av[4];
        #pragma unroll
        for (int i = 0; i < 4; i++)
            av[i] = *reinterpret_cast<const float4*>(&sA[(ty * 4 + i) * 128 + k4]);
        #pragma unroll
        for (int kk = 0; kk < 4; kk++) {
            const float4 w = *reinterpret_cast<const float4*>(&sW[(k4 + kk) * 64 + tx * 4]);
            #pragma unroll
            for (int i = 0; i < 4; i++) {
                const float a = (&av[i].x)[kk];
                acc[i][0] = fmaf(a, w.x, acc[i][0]);
                acc[i][1] = fmaf(a, w.y, acc[i][1]);
                acc[i][2] = fmaf(a, w.z, acc[i][2]);
                acc[i][3] = fmaf(a, w.w, acc[i][3]);
            }
        }
    }

    const float4 b = *reinterpret_cast<const float4*>(&bv[ch + tx * 4]);
    #pragma unroll
    for (int i = 0; i < 4; i++) {
        const int row = r0 + ty * 4 + i;           // s*MPIX + m
        const int s   = row / MPIX;
        const int m   = row - s * MPIX;
        const int py  = m / WSZ;
        const int px  = m - py * WSZ;
        unsigned char* dst = g_val + (size_t)s * IMGSZ
                           + ((py + 1) * PADW + (px + 1)) * CDIM + ch + tx * 4;
        const __nv_fp8x2_storage_t p0 = __nv_cvt_float2_to_fp8x2(
            make_float2(acc[i][0] + b.x, acc[i][1] + b.y), __NV_SATFINITE, __NV_E4M3);
        const __nv_fp8x2_storage_t p1 = __nv_cvt_float2_to_fp8x2(
            make_float2(acc[i][2] + b.z, acc[i][3] + b.w), __NV_SATFINITE, __NV_E4M3);
        const unsigned u = (unsigned)p0 | ((unsigned)p1 << 16);
        *reinterpret_cast<unsigned*>(dst) = u;
    }
}

// ---------------------------------------------------------------------------
// Kernel C: bilinear sampling on the padded fp8 image, SOFTWARE-PIPELINED
// camera loop: stage1+gathers for camera j+1 issue before decode of camera j
// (double-buffered raw/wcs; ~10 loads in flight per warp).
// ---------------------------------------------------------------------------
__global__ void k_sample(const float* __restrict__ refpts,   // (S,1,N,4,2)
                         const int* __restrict__ bmask) {    // (S,1,N,4) 4-byte flags
    const int n      = blockIdx.x;
    const int t      = threadIdx.x;
    const int h      = t >> 5;
    const int lane   = t & 31;
    const int chgrp  = lane & 1;
    const int corner = (lane >> 1) & 3;
    const int dx     = corner & 1, dy = corner >> 1;
    const int pt     = (lane >> 3) & 3;

    const float sgx = dx ? 1.f : -1.f, bxc = dx ? 0.f : 1.f;
    const float sgy = dy ? 1.f : -1.f, byc = dy ? 0.f : 1.f;
    const int cornerOff = (dy * PADW + dx) * CDIM;
    const int laneOff = (PADW + 1) * CDIM + cornerOff + h * DHEAD + chgrp * 16;

    __shared__ float sOff[OFF_W];
    __shared__ float sAw[ATTN_W];
    __shared__ float sRef[SCAM * 8];
    __shared__ int   sAct[SCAM];
    __shared__ int   sCnt;

    for (int i = t; i < OFF_W; i += 128)  sOff[i] = g_off[n * OFF_W + i];
    for (int i = t; i < ATTN_W; i += 128) sAw[i]  = g_aw[n * ATTN_W + i];
    for (int i = t; i < SCAM * 8; i += 128) {
        const int s = i >> 3, e = i & 7;
        sRef[i] = refpts[((size_t)s * NQ + n) * 8 + e];
    }
    if (t == 0) {
        int cnt = 0;
        #pragma unroll
        for (int s = 0; s < SCAM; s++) {
            const int4 mw = *reinterpret_cast<const int4*>(bmask + ((size_t)s * NQ + n) * DANCH);
            if (mw.x | mw.y | mw.z | mw.w) sAct[cnt++] = s;
        }
        sCnt = cnt;
    }
    __syncthreads();

    float ox[5], oy[5], wp[5];
    #pragma unroll
    for (int i = 0; i < 5; i++) {
        const int p = 4 * i + pt;
        ox[i] = sOff[h * 40 + p * 2 + 0];
        oy[i] = sOff[h * 40 + p * 2 + 1];
        wp[i] = sAw[h * POINTS + p];
    }

    __half2 hacc[8];
    #pragma unroll
    for (int q = 0; q < 8; q++) hacc[q] = __half2half2(__ushort_as_half(0));

    const int cnt = sCnt;

    // double-buffered staging
    float wcs[2][5];
    uint4 raw[2][5];

    // stage1 + issue gathers for camera slot jj into buffer b
    auto stage = [&](int jj, int b) {
        const int s = sAct[jj];
        const unsigned char* __restrict__ imgb = g_val + (size_t)s * IMGSZ + laneOff;
        const float fx = sRef[s * 8 + pt * 2 + 0];
        const float fy = sRef[s * 8 + pt * 2 + 1];
        int offs[5];
        #pragma unroll
        for (int i = 0; i < 5; i++) {
            float x = (fx + ox[i]) * 88.f - 0.5f;
            float y = (fy + oy[i]) * 32.f - 0.5f;
            x = fminf(fmaxf(x, -1.f), 88.f);
            y = fminf(fmaxf(y, -1.f), 32.f);
            const int x0 = __float2int_rd(x);
            const int y0 = __float2int_rd(y);
            const float wx = x - (float)x0;
            const float wy = y - (float)y0;
            wcs[b][i] = fmaf(sgx, wx, bxc) * fmaf(sgy, wy, byc) * wp[i];
            offs[i] = (y0 * PADW + x0) * CDIM;
        }
        #pragma unroll
        for (int i = 0; i < 5; i++)
            raw[b][i] = *reinterpret_cast<const uint4*>(imgb + offs[i]);
    };

    if (cnt > 0) stage(0, 0);

    for (int j = 0; j < cnt; j++) {
        const int buf = j & 1;
        if (j + 1 < cnt) stage(j + 1, buf ^ 1);

        #pragma unroll
        for (int i = 0; i < 5; i++) {
            const __half2 wch = __float2half2_rn(wcs[buf][i]);
            const unsigned rw[4] = {raw[buf][i].x, raw[buf][i].y, raw[buf][i].z, raw[buf][i].w};
            #pragma unroll
            for (int q = 0; q < 4; q++) {
                const __half2_raw lor = __nv_cvt_fp8x2_to_halfraw2(
                    (__nv_fp8x2_storage_t)(rw[q] & 0xffffu), __NV_E4M3);
                const __half2_raw hir = __nv_cvt_fp8x2_to_halfraw2(
                    (__nv_fp8x2_storage_t)(rw[q] >> 16), __NV_E4M3);
                hacc[q * 2 + 0] = __hfma2(wch, *reinterpret_cast<const __half2*>(&lor),
                                          hacc[q * 2 + 0]);
                hacc[q * 2 + 1] = __hfma2(wch, *reinterpret_cast<const __half2*>(&hir),
                                          hacc[q * 2 + 1]);
            }
        }
    }

    float acc[16];
    #pragma unroll
    for (int q = 0; q < 8; q++) {
        const float2 f = __half22float2(hacc[q]);
        acc[q * 2 + 0] = f.x;
        acc[q * 2 + 1] = f.y;
    }

    #pragma unroll
    for (int m = 2; m <= 16; m <<= 1)
        #pragma unroll
        for (int i = 0; i < 16; i++)
            acc[i] += __shfl_xor_sync(0xffffffffu, acc[i], m);

    if (lane < 2) {
        const float inv = 1.f / fmaxf((float)cnt, 1.0f);
        float* dst = g_slots + (size_t)n * CDIM + h * DHEAD + chgrp * 16;
        #pragma unroll
        for (int q = 0; q < 4; q++) {
            float4 o = make_float4(acc[q * 4 + 0] * inv, acc[q * 4 + 1] * inv,
                                   acc[q * 4 + 2] * inv, acc[q * 4 + 3] * inv);
            *reinterpret_cast<float4*>(dst + q * 4) = o;
        }
    }
}

// ---------------------------------------------------------------------------
// Kernel D (reverted to R12): 64 rows x 64-col half, 256 threads, grid 200.
// ---------------------------------------------------------------------------
__global__ void k_out_t(const float* __restrict__ query,
                        const float* __restrict__ Wout,
                        const float* __restrict__ bout,
                        float* __restrict__ out) {
    extern __shared__ float smem[];
    float* sW = smem;                 // [128][64]
    float* sA = smem + 128 * 64;      // [64][128]

    const int bx  = blockIdx.x;
    const int r0  = (bx >> 1) * TM;
    const int ch  = (bx & 1) * 64;
    const int tid = threadIdx.x;

    for (int idx = tid; idx < 128 * 16; idx += 256) {
        const int k = idx >> 4, c4 = idx & 15;
        reinterpret_cast<float4*>(sW)[idx] =
            *reinterpret_cast<const float4*>(&Wout[k * 128 + ch + c4 * 4]);
    }
    for (int idx = tid; idx < TM * 128 / 4; idx += 256)
        reinterpret_cast<float4*>(sA)[idx] =
            reinterpret_cast<const float4*>(g_slots + (size_t)r0 * CDIM)[idx];
    __syncthreads();

    const int ty = tid >> 4;
    const int tx = tid & 15;

    float acc[4][4];
    #pragma unroll
    for (int i = 0; i < 4; i++)
        #pragma unroll
        for (int j = 0; j < 4; j++) acc[i][j] = 0.f;

    for (int k4 = 0; k4 < 128; k4 += 4) {
        float4 av[4];
        #pragma unroll
        for (int i = 0; i < 4; i++)
            av[i] = *reinterpret_cast<const float4*>(&sA[(ty * 4 + i) * 128 + k4]);
        #pragma unroll
        for (int kk = 0; kk < 4; kk++) {
            const float4 w = *reinterpret_cast<const float4*>(&sW[(k4 + kk) * 64 + tx * 4]);
            #pragma unroll
            for (int i = 0; i < 4; i++) {
                const float a = (&av[i].x)[kk];
                acc[i][0] = fmaf(a, w.x, acc[i][0]);
                acc[i][1] = fmaf(a, w.y, acc[i][1]);
                acc[i][2] = fmaf(a, w.z, acc[i][2]);
                acc[i][3] = fmaf(a, w.w, acc[i][3]);
            }
        }
    }

    const float4 b = *reinterpret_cast<const float4*>(&bout[ch + tx * 4]);
    #pragma unroll
    for (int i = 0; i < 4; i++) {
        const int row = r0 + ty * 4 + i;
        const float4 q = *reinterpret_cast<const float4*>(&query[row * CDIM + ch + tx * 4]);
        float4 o = make_float4(acc[i][0] + b.x + q.x, acc[i][1] + b.y + q.y,
                               acc[i][2] + b.z + q.z, acc[i][3] + b.w + q.w);
        *reinterpret_cast<float4*>(&out[row * CDIM + ch + tx * 4]) = o;
    }
}

// ---------------------------------------------------------------------------
// Launch.
// ---------------------------------------------------------------------------
extern "C" void kernel_launch(void* const* d_in, const int* in_sizes, int n_in,
                              void* d_out, int out_size) {
    const float* query = (const float*)d_in[0];
    const float* value = (const float*)d_in[2];
    const float* qpos  = (const float*)d_in[3];
    const float* refp  = (const float*)d_in[4];
    const int*   bmask = (const int*)d_in[5];
    const float* Wv    = (const float*)d_in[8];
    const float* bv    = (const float*)d_in[9];
    const float* Woff  = (const float*)d_in[10];
    const float* boff  = (const float*)d_in[11];
    const float* Wattn = (const float*)d_in[12];
    const float* battn = (const float*)d_in[13];
    const float* Wout  = (const float*)d_in[14];
    const float* bout  = (const float*)d_in[15];
    float* out = (float*)d_out;

    const int smemA = (128 * ACOLS + TM * 128) * sizeof(float);   // 73728
    const int smemH = (128 * 64 + TM * 128) * sizeof(float);      // 65536

    cudaFuncSetAttribute(k_proj_off_attn_t, cudaFuncAttributeMaxDynamicSharedMemorySize, smemA);
    cudaFuncSetAttribute(k_proj_val_t,      cudaFuncAttributeMaxDynamicSharedMemorySize, smemH);
    cudaFuncSetAttribute(k_out_t,           cudaFuncAttributeMaxDynamicSharedMemorySize, smemH);

    // Fork: A on the aux stream, B on the main stream; join before sampling.
    cudaEventRecord(g_aux.evFork, 0);
    cudaStreamWaitEvent(g_aux.s, g_aux.evFork, 0);
    k_proj_off_attn_t<<<(NQ / TM) * 3, 256, smemA, g_aux.s>>>(query, qpos, Woff, boff, Wattn, battn);
    cudaEventRecord(g_aux.evJoin, g_aux.s);

    k_proj_val_t<<<(SCAM * MPIX / TM) * 2, 256, smemH>>>(value, Wv, bv);
    cudaStreamWaitEvent(0, g_aux.evJoin, 0);

    k_sample<<<NQ, CDIM>>>(refp, bmask);
    k_out_t<<<(NQ / TM) * 2, 256, smemH>>>(query, Wout, bout, out);
}

// round 15
// speedup vs baseline: 1.3226x; 1.3226x over previous
#include <cuda_runtime.h>
#include <cuda_bf16.h>
#include <cuda_fp8.h>
#include <cuda_fp16.h>
#include <math.h>

// Problem constants
#define NQ      6400
#define CDIM    128
#define SCAM    6
#define MPIX    2816     // 32*88
#define HEADS   4
#define POINTS  20
#define HSZ     32
#define WSZ     88
#define DHEAD   32
#define DANCH   4
#define OFF_W   160      // HEADS*POINTS*2
#define ATTN_W  80       // HEADS*POINTS
#define NCOMB   240      // OFF_W + ATTN_W

#define TM      64       // rows per GEMM block
#define ACOLS   80       // columns per kernel-A part

// Padded value image: x in [-1, 89] (91 cols), y in [-1, 33] (35 rows).
// Borders never written; device globals zero-initialized -> zero padding.
#define PADW    91
#define PADH    35
#define IMGSZ   (PADH * PADW * CDIM)

// Scratch (device globals -- no allocation allowed)
__device__ float         g_off[NQ * OFF_W];
__device__ float         g_aw [NQ * ATTN_W];
__device__ unsigned char g_val[SCAM * IMGSZ];            // padded fp8 e4m3 value image
__device__ float         g_slots[NQ * CDIM];

// Aux stream for A||B overlap -- created once in a static initializer.
namespace {
struct AuxStream {
    cudaStream_t s;
    cudaEvent_t evFork, evJoin;
    AuxStream() {
        cudaStreamCreateWithFlags(&s, cudaStreamNonBlocking);
        cudaEventCreateWithFlags(&evFork, cudaEventDisableTiming);
        cudaEventCreateWithFlags(&evJoin, cudaEventDisableTiming);
    }
};
AuxStream g_aux;
}

// ---------------------------------------------------------------------------
// Kernel A (unchanged, 3-way col-split)
// ---------------------------------------------------------------------------
__global__ void k_proj_off_attn_t(const float* __restrict__ query,
                                  const float* __restrict__ qpos,
                                  const float* __restrict__ Woff,
                                  const float* __restrict__ boff,
                                  const float* __restrict__ Wattn,
                                  const float* __restrict__ battn) {
    extern __shared__ float smem[];
    float* sW = smem;                 // [128][80]
    float* sA = smem + 128 * ACOLS;   // [64][128]

    const int bx   = blockIdx.x;
    const int n0   = (bx / 3) * TM;
    const int part = bx % 3;
    const int tid  = threadIdx.x;

    if (part < 2) {
        for (int idx = tid; idx < 128 * 20; idx += 256) {
            const int k = idx / 20, c4 = idx % 20;
            reinterpret_cast<float4*>(sW)[idx] =
                *reinterpret_cast<const float4*>(&Woff[k * OFF_W + part * ACOLS + c4 * 4]);
        }
    } else {
        for (int idx = tid; idx < 128 * 20; idx += 256)
            reinterpret_cast<float4*>(sW)[idx] = reinterpret_cast<const float4*>(Wattn)[idx];
    }
    for (int idx = tid; idx < TM * 128 / 4; idx += 256) {
        const float4 q4 = reinterpret_cast<const float4*>(query + (size_t)n0 * CDIM)[idx];
        const float4 p4 = reinterpret_cast<const float4*>(qpos + (size_t)n0 * CDIM)[idx];
        reinterpret_cast<float4*>(sA)[idx] =
            make_float4(q4.x + p4.x, q4.y + p4.y, q4.z + p4.z, q4.w + p4.w);
    }
    __syncthreads();

    const int ty = tid >> 4;
    const int tx = tid & 15;

    float acc[4][5];
    #pragma unroll
    for (int i = 0; i < 4; i++)
        #pragma unroll
        for (int j = 0; j < 5; j++) acc[i][j] = 0.f;

    #pragma unroll 4
    for (int k = 0; k < 128; k++) {
        float a[4];
        #pragma unroll
        for (int i = 0; i < 4; i++) a[i] = sA[(ty * 4 + i) * 128 + k];
        #pragma unroll
        for (int j = 0; j < 5; j++) {
            const float w = sW[k * ACOLS + tx + 16 * j];
            #pragma unroll
            for (int i = 0; i < 4; i++) acc[i][j] = fmaf(a[i], w, acc[i][j]);
        }
    }

    if (part < 2) {
        #pragma unroll
        for (int i = 0; i < 4; i++) {
            const int r = n0 + ty * 4 + i;
            #pragma unroll
            for (int j = 0; j < 5; j++) {
                const int c = tx + 16 * j;
                const int t = part * ACOLS + c;
                const float v = acc[i][j] + boff[t];
                g_off[(size_t)r * OFF_W + t] = v * ((t & 1) ? (1.f / 32.f) : (1.f / 88.f));
            }
        }
    } else {
        __syncthreads();
        #pragma unroll
        for (int i = 0; i < 4; i++)
            #pragma unroll
            for (int j = 0; j < 5; j++)
                sW[(ty * 4 + i) * ACOLS + tx + 16 * j] = acc[i][j];
        __syncthreads();

        const int r = tid >> 2, h = tid & 3;
        float lg[POINTS];
        float mx = -1e30f;
        #pragma unroll
        for (int p = 0; p < POINTS; p++) {
            lg[p] = sW[r * ACOLS + h * POINTS + p] + battn[h * POINTS + p];
            mx = fmaxf(mx, lg[p]);
        }
        float sum = 0.f;
        #pragma unroll
        for (int p = 0; p < POINTS; p++) { lg[p] = __expf(lg[p] - mx); sum += lg[p]; }
        const float inv = 1.f / sum;
        #pragma unroll
        for (int p = 0; p < POINTS; p++)
            g_aw[(size_t)(n0 + r) * ATTN_W + h * POINTS + p] = lg[p] * inv;
    }
}

// ---------------------------------------------------------------------------
// Kernel B (unchanged, col-split, padded-image store)
// ---------------------------------------------------------------------------
__global__ void k_proj_val_t(const float* __restrict__ value,
                             const float* __restrict__ Wv,
                             const float* __restrict__ bv) {
    extern __shared__ float smem[];
    float* sW = smem;                 // [128][64]
    float* sA = smem + 128 * 64;      // [64][128]

    const int bx  = blockIdx.x;
    const int r0  = (bx >> 1) * TM;
    const int ch  = (bx & 1) * 64;
    const int tid = threadIdx.x;

    for (int idx = tid; idx < 128 * 16; idx += 256) {
        const int k = idx >> 4, c4 = idx & 15;
        reinterpret_cast<float4*>(sW)[idx] =
            *reinterpret_cast<const float4*>(&Wv[k * 128 + ch + c4 * 4]);
    }
    for (int idx = tid; idx < TM * 128 / 4; idx += 256)
        reinterpret_cast<float4*>(sA)[idx] =
            reinterpret_cast<const float4*>(value + (size_t)r0 * CDIM)[idx];
    __syncthreads();

    const int ty = tid >> 4;
    const int tx = tid & 15;

    float acc[4][4];
    #pragma unroll
    for (int i = 0; i < 4; i++)
        #pragma unroll
        for (int j = 0; j < 4; j++) acc[i][j] = 0.f;

    for (int k4 = 0; k4 < 128; k4 += 4) {
        float4 av[4];
        #pragma unroll
        for (int i = 0; i < 4; i++)
            av[i] = *reinterpret_cast<const float4*>(&sA[(ty * 4 + i) * 128 + k4]);
        #pragma unroll
        for (int kk = 0; kk < 4; kk++) {
            const float4 w = *reinterpret_cast<const float4*>(&sW[(k4 + kk) * 64 + tx * 4]);
            #pragma unroll
            for (int i = 0; i < 4; i++) {
                const float a = (&av[i].x)[kk];
                acc[i][0] = fmaf(a, w.x, acc[i][0]);
                acc[i][1] = fmaf(a, w.y, acc[i][1]);
                acc[i][2] = fmaf(a, w.z, acc[i][2]);
                acc[i][3] = fmaf(a, w.w, acc[i][3]);
            }
        }
    }

    const float4 b = *reinterpret_cast<const float4*>(&bv[ch + tx * 4]);
    #pragma unroll
    for (int i = 0; i < 4; i++) {
        const int row = r0 + ty * 4 + i;           // s*MPIX + m
        const int s   = row / MPIX;
        const int m   = row - s * MPIX;
        const int py  = m / WSZ;
        const int px  = m - py * WSZ;
        unsigned char* dst = g_val + (size_t)s * IMGSZ
                           + ((py + 1) * PADW + (px + 1)) * CDIM + ch + tx * 4;
        const __nv_fp8x2_storage_t p0 = __nv_cvt_float2_to_fp8x2(
            make_float2(acc[i][0] + b.x, acc[i][1] + b.y), __NV_SATFINITE, __NV_E4M3);
        const __nv_fp8x2_storage_t p1 = __nv_cvt_float2_to_fp8x2(
            make_float2(acc[i][2] + b.z, acc[i][3] + b.w), __NV_SATFINITE, __NV_E4M3);
        const unsigned u = (unsigned)p0 | ((unsigned)p1 << 16);
        *reinterpret_cast<unsigned*>(dst) = u;
    }
}

// ---------------------------------------------------------------------------
// Kernel C: bilinear sampling on the padded fp8 image.
// Software-pipelined camera loop with STATIC double buffers (rawA/rawB,
// wcsA/wcsB) -- all array indices compile-time, everything stays in
// registers (no dynamic indexing -> no local-memory spills, the R14 bug).
// ---------------------------------------------------------------------------
struct SampCtx {
    const unsigned char* valBase;   // g_val + laneOff
    const float* sRef;
    const int*   sAct;
    float sgx, bxc, sgy, byc;
    int pt;
    float ox[5], oy[5], wp[5];
};

__device__ __forceinline__ void samp_stage(const SampCtx& c, int jj,
                                           float (&wcs)[5], uint4 (&raw)[5]) {
    const int s = c.sAct[jj];
    const unsigned char* __restrict__ imgb = c.valBase + (size_t)s * IMGSZ;
    const float fx = c.sRef[s * 8 + c.pt * 2 + 0];
    const float fy = c.sRef[s * 8 + c.pt * 2 + 1];
    int offs[5];
    #pragma unroll
    for (int i = 0; i < 5; i++) {
        float x = (fx + c.ox[i]) * 88.f - 0.5f;
        float y = (fy + c.oy[i]) * 32.f - 0.5f;
        x = fminf(fmaxf(x, -1.f), 88.f);
        y = fminf(fmaxf(y, -1.f), 32.f);
        const int x0 = __float2int_rd(x);
        const int y0 = __float2int_rd(y);
        const float wx = x - (float)x0;
        const float wy = y - (float)y0;
        wcs[i] = fmaf(c.sgx, wx, c.bxc) * fmaf(c.sgy, wy, c.byc) * c.wp[i];
        offs[i] = (y0 * PADW + x0) * CDIM;
    }
    #pragma unroll
    for (int i = 0; i < 5; i++)
        raw[i] = *reinterpret_cast<const uint4*>(imgb + offs[i]);
}

__device__ __forceinline__ void samp_consume(const float (&wcs)[5], const uint4 (&raw)[5],
                                             __half2 (&hacc)[8]) {
    #pragma unroll
    for (int i = 0; i < 5; i++) {
        const __half2 wch = __float2half2_rn(wcs[i]);
        const unsigned rw[4] = {raw[i].x, raw[i].y, raw[i].z, raw[i].w};
        #pragma unroll
        for (int q = 0; q < 4; q++) {
            const __half2_raw lor = __nv_cvt_fp8x2_to_halfraw2(
                (__nv_fp8x2_storage_t)(rw[q] & 0xffffu), __NV_E4M3);
            const __half2_raw hir = __nv_cvt_fp8x2_to_halfraw2(
                (__nv_fp8x2_storage_t)(rw[q] >> 16), __NV_E4M3);
            hacc[q * 2 + 0] = __hfma2(wch, *reinterpret_cast<const __half2*>(&lor),
                                      hacc[q * 2 + 0]);
            hacc[q * 2 + 1] = __hfma2(wch, *reinterpret_cast<const __half2*>(&hir),
                                      hacc[q * 2 + 1]);
        }
    }
}

__global__ void k_sample(const float* __restrict__ refpts,   // (S,1,N,4,2)
                         const int* __restrict__ bmask) {    // (S,1,N,4) 4-byte flags
    const int n      = blockIdx.x;
    const int t      = threadIdx.x;
    const int h      = t >> 5;
    const int lane   = t & 31;
    const int chgrp  = lane & 1;
    const int corner = (lane >> 1) & 3;
    const int dx     = corner & 1, dy = corner >> 1;
    const int pt     = (lane >> 3) & 3;

    const int cornerOff = (dy * PADW + dx) * CDIM;
    const int laneOff = (PADW + 1) * CDIM + cornerOff + h * DHEAD + chgrp * 16;

    __shared__ float sOff[OFF_W];
    __shared__ float sAw[ATTN_W];
    __shared__ float sRef[SCAM * 8];
    __shared__ int   sAct[SCAM];
    __shared__ int   sCnt;

    for (int i = t; i < OFF_W; i += 128)  sOff[i] = g_off[n * OFF_W + i];
    for (int i = t; i < ATTN_W; i += 128) sAw[i]  = g_aw[n * ATTN_W + i];
    for (int i = t; i < SCAM * 8; i += 128) {
        const int s = i >> 3, e = i & 7;
        sRef[i] = refpts[((size_t)s * NQ + n) * 8 + e];
    }
    if (t == 0) {
        int cnt = 0;
        #pragma unroll
        for (int s = 0; s < SCAM; s++) {
            const int4 mw = *reinterpret_cast<const int4*>(bmask + ((size_t)s * NQ + n) * DANCH);
            if (mw.x | mw.y | mw.z | mw.w) sAct[cnt++] = s;
        }
        sCnt = cnt;
    }
    __syncthreads();

    SampCtx ctx;
    ctx.valBase = g_val + laneOff;
    ctx.sRef = sRef;
    ctx.sAct = sAct;
    ctx.sgx = dx ? 1.f : -1.f;  ctx.bxc = dx ? 0.f : 1.f;
    ctx.sgy = dy ? 1.f : -1.f;  ctx.byc = dy ? 0.f : 1.f;
    ctx.pt = pt;
    #pragma unroll
    for (int i = 0; i < 5; i++) {
        const int p = 4 * i + pt;
        ctx.ox[i] = sOff[h * 40 + p * 2 + 0];
        ctx.oy[i] = sOff[h * 40 + p * 2 + 1];
        ctx.wp[i] = sAw[h * POINTS + p];
    }

    __half2 hacc[8];
    #pragma unroll
    for (int q = 0; q < 8; q++) hacc[q] = __half2half2(__ushort_as_half(0));

    const int cnt = sCnt;

    // static double buffers: all indices compile-time
    float wcsA[5], wcsB[5];
    uint4 rawA[5], rawB[5];

    if (cnt > 0) {
        samp_stage(ctx, 0, wcsA, rawA);
        int j = 0;
        while (true) {
            // current in A
            if (j + 1 < cnt) samp_stage(ctx, j + 1, wcsB, rawB);
            samp_consume(wcsA, rawA, hacc);
            j++;
            if (j >= cnt) break;
            // current in B
            if (j + 1 < cnt) samp_stage(ctx, j + 1, wcsA, rawA);
            samp_consume(wcsB, rawB, hacc);
            j++;
            if (j >= cnt) break;
        }
    }

    float acc[16];
    #pragma unroll
    for (int q = 0; q < 8; q++) {
        const float2 f = __half22float2(hacc[q]);
        acc[q * 2 + 0] = f.x;
        acc[q * 2 + 1] = f.y;
    }

    #pragma unroll
    for (int m = 2; m <= 16; m <<= 1)
        #pragma unroll
        for (int i = 0; i < 16; i++)
            acc[i] += __shfl_xor_sync(0xffffffffu, acc[i], m);

    if (lane < 2) {
        const float inv = 1.f / fmaxf((float)cnt, 1.0f);
        float* dst = g_slots + (size_t)n * CDIM + h * DHEAD + chgrp * 16;
        #pragma unroll
        for (int q = 0; q < 4; q++) {
            float4 o = make_float4(acc[q * 4 + 0] * inv, acc[q * 4 + 1] * inv,
                                   acc[q * 4 + 2] * inv, acc[q * 4 + 3] * inv);
            *reinterpret_cast<float4*>(dst + q * 4) = o;
        }
    }
}

// ---------------------------------------------------------------------------
// Kernel D (R12 shape): 64 rows x 64-col half, 256 threads, grid 200.
// ---------------------------------------------------------------------------
__global__ void k_out_t(const float* __restrict__ query,
                        const float* __restrict__ Wout,
                        const float* __restrict__ bout,
                        float* __restrict__ out) {
    extern __shared__ float smem[];
    float* sW = smem;                 // [128][64]
    float* sA = smem + 128 * 64;      // [64][128]

    const int bx  = blockIdx.x;
    const int r0  = (bx >> 1) * TM;
    const int ch  = (bx & 1) * 64;
    const int tid = threadIdx.x;

    for (int idx = tid; idx < 128 * 16; idx += 256) {
        const int k = idx >> 4, c4 = idx & 15;
        reinterpret_cast<float4*>(sW)[idx] =
            *reinterpret_cast<const float4*>(&Wout[k * 128 + ch + c4 * 4]);
    }
    for (int idx = tid; idx < TM * 128 / 4; idx += 256)
        reinterpret_cast<float4*>(sA)[idx] =
            reinterpret_cast<const float4*>(g_slots + (size_t)r0 * CDIM)[idx];
    __syncthreads();

    const int ty = tid >> 4;
    const int tx = tid & 15;

    float acc[4][4];
    #pragma unroll
    for (int i = 0; i < 4; i++)
        #pragma unroll
        for (int j = 0; j < 4; j++) acc[i][j] = 0.f;

    for (int k4 = 0; k4 < 128; k4 += 4) {
        float4 av[4];
        #pragma unroll
        for (int i = 0; i < 4; i++)
            av[i] = *reinterpret_cast<const float4*>(&sA[(ty * 4 + i) * 128 + k4]);
        #pragma unroll
        for (int kk = 0; kk < 4; kk++) {
            const float4 w = *reinterpret_cast<const float4*>(&sW[(k4 + kk) * 64 + tx * 4]);
            #pragma unroll
            for (int i = 0; i < 4; i++) {
                const float a = (&av[i].x)[kk];
                acc[i][0] = fmaf(a, w.x, acc[i][0]);
                acc[i][1] = fmaf(a, w.y, acc[i][1]);
                acc[i][2] = fmaf(a, w.z, acc[i][2]);
                acc[i][3] = fmaf(a, w.w, acc[i][3]);
            }
        }
    }

    const float4 b = *reinterpret_cast<const float4*>(&bout[ch + tx * 4]);
    #pragma unroll
    for (int i = 0; i < 4; i++) {
        const int row = r0 + ty * 4 + i;
        const float4 q = *reinterpret_cast<const float4*>(&query[row * CDIM + ch + tx * 4]);
        float4 o = make_float4(acc[i][0] + b.x + q.x, acc[i][1] + b.y + q.y,
                               acc[i][2] + b.z + q.z, acc[i][3] + b.w + q.w);
        *reinterpret_cast<float4*>(&out[row * CDIM + ch + tx * 4]) = o;
    }
}

// ---------------------------------------------------------------------------
// Launch.
// ---------------------------------------------------------------------------
extern "C" void kernel_launch(void* const* d_in, const int* in_sizes, int n_in,
                              void* d_out, int out_size) {
    const float* query = (const float*)d_in[0];
    const float* value = (const float*)d_in[2];
    const float* qpos  = (const float*)d_in[3];
    const float* refp  = (const float*)d_in[4];
    const int*   bmask = (const int*)d_in[5];
    const float* Wv    = (const float*)d_in[8];
    const float* bv    = (const float*)d_in[9];
    const float* Woff  = (const float*)d_in[10];
    const float* boff  = (const float*)d_in[11];
    const float* Wattn = (const float*)d_in[12];
    const float* battn = (const float*)d_in[13];
    const float* Wout  = (const float*)d_in[14];
    const float* bout  = (const float*)d_in[15];
    float* out = (float*)d_out;

    const int smemA = (128 * ACOLS + TM * 128) * sizeof(float);   // 73728
    const int smemH = (128 * 64 + TM * 128) * sizeof(float);      // 65536

    cudaFuncSetAttribute(k_proj_off_attn_t, cudaFuncAttributeMaxDynamicSharedMemorySize, smemA);
    cudaFuncSetAttribute(k_proj_val_t,      cudaFuncAttributeMaxDynamicSharedMemorySize, smemH);
    cudaFuncSetAttribute(k_out_t,           cudaFuncAttributeMaxDynamicSharedMemorySize, smemH);

    // Fork: A on the aux stream, B on the main stream; join before sampling.
    cudaEventRecord(g_aux.evFork, 0);
    cudaStreamWaitEvent(g_aux.s, g_aux.evFork, 0);
    k_proj_off_attn_t<<<(NQ / TM) * 3, 256, smemA, g_aux.s>>>(query, qpos, Woff, boff, Wattn, battn);
    cudaEventRecord(g_aux.evJoin, g_aux.s);

    k_proj_val_t<<<(SCAM * MPIX / TM) * 2, 256, smemH>>>(value, Wv, bv);
    cudaStreamWaitEvent(0, g_aux.evJoin, 0);

    k_sample<<<NQ, CDIM>>>(refp, bmask);
    k_out_t<<<(NQ / TM) * 2, 256, smemH>>>(query, Wout, bout, out);
}

// round 16
// speedup vs baseline: 1.5061x; 1.1388x over previous
#include <cuda_runtime.h>
#include <cuda_bf16.h>
#include <cuda_fp8.h>
#include <cuda_fp16.h>
#include <math.h>

// Problem constants
#define NQ      6400
#define CDIM    128
#define SCAM    6
#define MPIX    2816     // 32*88
#define HEADS   4
#define POINTS  20
#define HSZ     32
#define WSZ     88
#define DHEAD   32
#define DANCH   4
#define OFF_W   160      // HEADS*POINTS*2
#define ATTN_W  80       // HEADS*POINTS
#define NCOMB   240      // OFF_W + ATTN_W

#define TM      64       // rows per GEMM block
#define ACOLS   80       // columns per kernel-A part

// Padded value image: x in [-1, 89] (91 cols), y in [-1, 33] (35 rows).
// Borders never written; device globals zero-initialized -> zero padding.
#define PADW    91
#define PADH    35
#define IMGSZ   (PADH * PADW * CDIM)

// Scratch (device globals -- no allocation allowed)
__device__ float         g_off[NQ * OFF_W];
__device__ float         g_aw [NQ * ATTN_W];
__device__ unsigned char g_val[SCAM * IMGSZ];            // padded fp8 e4m3 value image
__device__ float         g_slots[NQ * CDIM];

// Aux stream for A||B overlap -- created once in a static initializer.
namespace {
struct AuxStream {
    cudaStream_t s;
    cudaEvent_t evFork, evJoin;
    AuxStream() {
        cudaStreamCreateWithFlags(&s, cudaStreamNonBlocking);
        cudaEventCreateWithFlags(&evFork, cudaEventDisableTiming);
        cudaEventCreateWithFlags(&evJoin, cudaEventDisableTiming);
    }
};
AuxStream g_aux;
}

// ---------------------------------------------------------------------------
// Kernel A (unchanged, 3-way col-split)
// ---------------------------------------------------------------------------
__global__ void k_proj_off_attn_t(const float* __restrict__ query,
                                  const float* __restrict__ qpos,
                                  const float* __restrict__ Woff,
                                  const float* __restrict__ boff,
                                  const float* __restrict__ Wattn,
                                  const float* __restrict__ battn) {
    extern __shared__ float smem[];
    float* sW = smem;                 // [128][80]
    float* sA = smem + 128 * ACOLS;   // [64][128]

    const int bx   = blockIdx.x;
    const int n0   = (bx / 3) * TM;
    const int part = bx % 3;
    const int tid  = threadIdx.x;

    if (part < 2) {
        for (int idx = tid; idx < 128 * 20; idx += 256) {
            const int k = idx / 20, c4 = idx % 20;
            reinterpret_cast<float4*>(sW)[idx] =
                *reinterpret_cast<const float4*>(&Woff[k * OFF_W + part * ACOLS + c4 * 4]);
        }
    } else {
        for (int idx = tid; idx < 128 * 20; idx += 256)
            reinterpret_cast<float4*>(sW)[idx] = reinterpret_cast<const float4*>(Wattn)[idx];
    }
    for (int idx = tid; idx < TM * 128 / 4; idx += 256) {
        const float4 q4 = reinterpret_cast<const float4*>(query + (size_t)n0 * CDIM)[idx];
        const float4 p4 = reinterpret_cast<const float4*>(qpos + (size_t)n0 * CDIM)[idx];
        reinterpret_cast<float4*>(sA)[idx] =
            make_float4(q4.x + p4.x, q4.y + p4.y, q4.z + p4.z, q4.w + p4.w);
    }
    __syncthreads();

    const int ty = tid >> 4;
    const int tx = tid & 15;

    float acc[4][5];
    #pragma unroll
    for (int i = 0; i < 4; i++)
        #pragma unroll
        for (int j = 0; j < 5; j++) acc[i][j] = 0.f;

    #pragma unroll 4
    for (int k = 0; k < 128; k++) {
        float a[4];
        #pragma unroll
        for (int i = 0; i < 4; i++) a[i] = sA[(ty * 4 + i) * 128 + k];
        #pragma unroll
        for (int j = 0; j < 5; j++) {
            const float w = sW[k * ACOLS + tx + 16 * j];
            #pragma unroll
            for (int i = 0; i < 4; i++) acc[i][j] = fmaf(a[i], w, acc[i][j]);
        }
    }

    if (part < 2) {
        #pragma unroll
        for (int i = 0; i < 4; i++) {
            const int r = n0 + ty * 4 + i;
            #pragma unroll
            for (int j = 0; j < 5; j++) {
                const int c = tx + 16 * j;
                const int t = part * ACOLS + c;
                const float v = acc[i][j] + boff[t];
                g_off[(size_t)r * OFF_W + t] = v * ((t & 1) ? (1.f / 32.f) : (1.f / 88.f));
            }
        }
    } else {
        __syncthreads();
        #pragma unroll
        for (int i = 0; i < 4; i++)
            #pragma unroll
            for (int j = 0; j < 5; j++)
                sW[(ty * 4 + i) * ACOLS + tx + 16 * j] = acc[i][j];
        __syncthreads();

        const int r = tid >> 2, h = tid & 3;
        float lg[POINTS];
        float mx = -1e30f;
        #pragma unroll
        for (int p = 0; p < POINTS; p++) {
            lg[p] = sW[r * ACOLS + h * POINTS + p] + battn[h * POINTS + p];
            mx = fmaxf(mx, lg[p]);
        }
        float sum = 0.f;
        #pragma unroll
        for (int p = 0; p < POINTS; p++) { lg[p] = __expf(lg[p] - mx); sum += lg[p]; }
        const float inv = 1.f / sum;
        #pragma unroll
        for (int p = 0; p < POINTS; p++)
            g_aw[(size_t)(n0 + r) * ATTN_W + h * POINTS + p] = lg[p] * inv;
    }
}

// ---------------------------------------------------------------------------
// Kernel B (unchanged, col-split, padded-image store)
// ---------------------------------------------------------------------------
__global__ void k_proj_val_t(const float* __restrict__ value,
                             const float* __restrict__ Wv,
                             const float* __restrict__ bv) {
    extern __shared__ float smem[];
    float* sW = smem;                 // [128][64]
    float* sA = smem + 128 * 64;      // [64][128]

    const int bx  = blockIdx.x;
    const int r0  = (bx >> 1) * TM;
    const int ch  = (bx & 1) * 64;
    const int tid = threadIdx.x;

    for (int idx = tid; idx < 128 * 16; idx += 256) {
        const int k = idx >> 4, c4 = idx & 15;
        reinterpret_cast<float4*>(sW)[idx] =
            *reinterpret_cast<const float4*>(&Wv[k * 128 + ch + c4 * 4]);
    }
    for (int idx = tid; idx < TM * 128 / 4; idx += 256)
        reinterpret_cast<float4*>(sA)[idx] =
            reinterpret_cast<const float4*>(value + (size_t)r0 * CDIM)[idx];
    __syncthreads();

    const int ty = tid >> 4;
    const int tx = tid & 15;

    float acc[4][4];
    #pragma unroll
    for (int i = 0; i < 4; i++)
        #pragma unroll
        for (int j = 0; j < 4; j++) acc[i][j] = 0.f;

    for (int k4 = 0; k4 < 128; k4 += 4) {
        float4 av[4];
        #pragma unroll
        for (int i = 0; i < 4; i++)
            av[i] = *reinterpret_cast<const float4*>(&sA[(ty * 4 + i) * 128 + k4]);
        #pragma unroll
        for (int kk = 0; kk < 4; kk++) {
            const float4 w = *reinterpret_cast<const float4*>(&sW[(k4 + kk) * 64 + tx * 4]);
            #pragma unroll
            for (int i = 0; i < 4; i++) {
                const float a = (&av[i].x)[kk];
                acc[i][0] = fmaf(a, w.x, acc[i][0]);
                acc[i][1] = fmaf(a, w.y, acc[i][1]);
                acc[i][2] = fmaf(a, w.z, acc[i][2]);
                acc[i][3] = fmaf(a, w.w, acc[i][3]);
            }
        }
    }

    const float4 b = *reinterpret_cast<const float4*>(&bv[ch + tx * 4]);
    #pragma unroll
    for (int i = 0; i < 4; i++) {
        const int row = r0 + ty * 4 + i;           // s*MPIX + m
        const int s   = row / MPIX;
        const int m   = row - s * MPIX;
        const int py  = m / WSZ;
        const int px  = m - py * WSZ;
        unsigned char* dst = g_val + (size_t)s * IMGSZ
                           + ((py + 1) * PADW + (px + 1)) * CDIM + ch + tx * 4;
        const __nv_fp8x2_storage_t p0 = __nv_cvt_float2_to_fp8x2(
            make_float2(acc[i][0] + b.x, acc[i][1] + b.y), __NV_SATFINITE, __NV_E4M3);
        const __nv_fp8x2_storage_t p1 = __nv_cvt_float2_to_fp8x2(
            make_float2(acc[i][2] + b.z, acc[i][3] + b.w), __NV_SATFINITE, __NV_E4M3);
        const unsigned u = (unsigned)p0 | ((unsigned)p1 << 16);
        *reinterpret_cast<unsigned*>(dst) = u;
    }
}

// ---------------------------------------------------------------------------
// Kernel C: bilinear sampling, LINE-COHERENT lane map.
// Block = query (128 threads). Warp w = point slot (p = 4i + w, anchor d = w).
// lane = corner(2b) | chgrp(3b): the 8 lanes of one corner read the FULL
// 128B pixel line (8 x 16B) -> 4 distinct lines per LDG instead of 16
// (4x fewer L1tex wavefronts). chgrp covers all heads: h = chgrp>>1.
// Corner reduction: xor 8, 16. Point slots combined across warps via smem.
// ---------------------------------------------------------------------------
__global__ void k_sample(const float* __restrict__ refpts,   // (S,1,N,4,2)
                         const int* __restrict__ bmask) {    // (S,1,N,4) 4-byte flags
    const int n      = blockIdx.x;
    const int t      = threadIdx.x;
    const int w      = t >> 5;           // warp = point slot = anchor d
    const int lane   = t & 31;
    const int corner = lane >> 3;
    const int chgrp  = lane & 7;         // 16-byte channel group (8 cover 128B)
    const int dx     = corner & 1, dy = corner >> 1;
    const int h      = chgrp >> 1;       // head of this lane's channels

    const float sgx = dx ? 1.f : -1.f, bxc = dx ? 0.f : 1.f;
    const float sgy = dy ? 1.f : -1.f, byc = dy ? 0.f : 1.f;
    const int cornerOff = (dy * PADW + dx) * CDIM;
    const int laneOff = (PADW + 1) * CDIM + cornerOff + chgrp * 16;

    __shared__ float sOff[OFF_W];
    __shared__ float sAw[ATTN_W];
    __shared__ float sRef[SCAM * 8];
    __shared__ int   sAct[SCAM];
    __shared__ int   sCnt;
    __shared__ float sPart[HEADS][CDIM];   // per-warp partial channel sums

    for (int i = t; i < OFF_W; i += 128)  sOff[i] = g_off[n * OFF_W + i];
    for (int i = t; i < ATTN_W; i += 128) sAw[i]  = g_aw[n * ATTN_W + i];
    for (int i = t; i < SCAM * 8; i += 128) {
        const int s = i >> 3, e = i & 7;
        sRef[i] = refpts[((size_t)s * NQ + n) * 8 + e];
    }
    if (t == 0) {
        int cnt = 0;
        #pragma unroll
        for (int s = 0; s < SCAM; s++) {
            const int4 mw = *reinterpret_cast<const int4*>(bmask + ((size_t)s * NQ + n) * DANCH);
            if (mw.x | mw.y | mw.z | mw.w) sAct[cnt++] = s;
        }
        sCnt = cnt;
    }
    __syncthreads();

    // hoist this lane's 5 points (p = 4i + w): offsets (head h) + attn weights
    float ox[5], oy[5], wp[5];
    #pragma unroll
    for (int i = 0; i < 5; i++) {
        const int p = 4 * i + w;
        ox[i] = sOff[h * 40 + p * 2 + 0];
        oy[i] = sOff[h * 40 + p * 2 + 1];
        wp[i] = sAw[h * POINTS + p];
    }

    __half2 hacc[8];
    #pragma unroll
    for (int q = 0; q < 8; q++) hacc[q] = __half2half2(__ushort_as_half(0));

    const int cnt = sCnt;
    for (int j = 0; j < cnt; j++) {
        const int s = sAct[j];
        const unsigned char* __restrict__ imgb = g_val + (size_t)s * IMGSZ + laneOff;
        const float fx = sRef[s * 8 + w * 2 + 0];   // anchor d = w
        const float fy = sRef[s * 8 + w * 2 + 1];

        // stage 1: coords, weights, addresses (branch-free; clamp + zero pad)
        float wcs[5];
        int   offs[5];
        #pragma unroll
        for (int i = 0; i < 5; i++) {
            float x = (fx + ox[i]) * 88.f - 0.5f;
            float y = (fy + oy[i]) * 32.f - 0.5f;
            x = fminf(fmaxf(x, -1.f), 88.f);
            y = fminf(fmaxf(y, -1.f), 32.f);
            const int x0 = __float2int_rd(x);
            const int y0 = __float2int_rd(y);
            const float wx = x - (float)x0;
            const float wy = y - (float)y0;
            wcs[i] = fmaf(sgx, wx, bxc) * fmaf(sgy, wy, byc) * wp[i];
            offs[i] = (y0 * PADW + x0) * CDIM;
        }

        // stage 2: issue all 5 gathers (full-line coverage per corner group)
        uint4 raw[5];
        #pragma unroll
        for (int i = 0; i < 5; i++)
            raw[i] = *reinterpret_cast<const uint4*>(imgb + offs[i]);

        // stage 3: decode + accumulate in half2
        #pragma unroll
        for (int i = 0; i < 5; i++) {
            const __half2 wch = __float2half2_rn(wcs[i]);
            const unsigned rw[4] = {raw[i].x, raw[i].y, raw[i].z, raw[i].w};
            #pragma unroll
            for (int q = 0; q < 4; q++) {
                const __half2_raw lor = __nv_cvt_fp8x2_to_halfraw2(
                    (__nv_fp8x2_storage_t)(rw[q] & 0xffffu), __NV_E4M3);
                const __half2_raw hir = __nv_cvt_fp8x2_to_halfraw2(
                    (__nv_fp8x2_storage_t)(rw[q] >> 16), __NV_E4M3);
                hacc[q * 2 + 0] = __hfma2(wch, *reinterpret_cast<const __half2*>(&lor),
                                          hacc[q * 2 + 0]);
                hacc[q * 2 + 1] = __hfma2(wch, *reinterpret_cast<const __half2*>(&hir),
                                          hacc[q * 2 + 1]);
            }
        }
    }

    // flush to fp32
    float acc[16];
    #pragma unroll
    for (int q = 0; q < 8; q++) {
        const float2 f = __half22float2(hacc[q]);
        acc[q * 2 + 0] = f.x;
        acc[q * 2 + 1] = f.y;
    }

    // reduce over corners (corner bits are lane bits 3,4)
    #pragma unroll
    for (int m = 8; m <= 16; m <<= 1)
        #pragma unroll
        for (int i = 0; i < 16; i++)
            acc[i] += __shfl_xor_sync(0xffffffffu, acc[i], m);

    // lanes 0..7 hold channels chgrp*16..+16 summed over this warp's points
    if (lane < 8) {
        #pragma unroll
        for (int k = 0; k < 16; k++)
            sPart[w][chgrp * 16 + k] = acc[k];
    }
    __syncthreads();

    // combine the 4 point-slot warps; divide by camera count
    {
        const float inv = 1.f / fmaxf((float)sCnt, 1.0f);
        const float v = (sPart[0][t] + sPart[1][t]) + (sPart[2][t] + sPart[3][t]);
        g_slots[(size_t)n * CDIM + t] = v * inv;
    }
}

// ---------------------------------------------------------------------------
// Kernel D (R12 shape): 64 rows x 64-col half, 256 threads, grid 200.
// ---------------------------------------------------------------------------
__global__ void k_out_t(const float* __restrict__ query,
                        const float* __restrict__ Wout,
                        const float* __restrict__ bout,
                        float* __restrict__ out) {
    extern __shared__ float smem[];
    float* sW = smem;                 // [128][64]
    float* sA = smem + 128 * 64;      // [64][128]

    const int bx  = blockIdx.x;
    const int r0  = (bx >> 1) * TM;
    const int ch  = (bx & 1) * 64;
    const int tid = threadIdx.x;

    for (int idx = tid; idx < 128 * 16; idx += 256) {
        const int k = idx >> 4, c4 = idx & 15;
        reinterpret_cast<float4*>(sW)[idx] =
            *reinterpret_cast<const float4*>(&Wout[k * 128 + ch + c4 * 4]);
    }
    for (int idx = tid; idx < TM * 128 / 4; idx += 256)
        reinterpret_cast<float4*>(sA)[idx] =
            reinterpret_cast<const float4*>(g_slots + (size_t)r0 * CDIM)[idx];
    __syncthreads();

    const int ty = tid >> 4;
    const int tx = tid & 15;

    float acc[4][4];
    #pragma unroll
    for (int i = 0; i < 4; i++)
        #pragma unroll
        for (int j = 0; j < 4; j++) acc[i][j] = 0.f;

    for (int k4 = 0; k4 < 128; k4 += 4) {
        float4 av[4];
        #pragma unroll
        for (int i = 0; i < 4; i++)
            av[i] = *reinterpret_cast<const float4*>(&sA[(ty * 4 + i) * 128 + k4]);
        #pragma unroll
        for (int kk = 0; kk < 4; kk++) {
            const float4 w = *reinterpret_cast<const float4*>(&sW[(k4 + kk) * 64 + tx * 4]);
            #pragma unroll
            for (int i = 0; i < 4; i++) {
                const float a = (&av[i].x)[kk];
                acc[i][0] = fmaf(a, w.x, acc[i][0]);
                acc[i][1] = fmaf(a, w.y, acc[i][1]);
                acc[i][2] = fmaf(a, w.z, acc[i][2]);
                acc[i][3] = fmaf(a, w.w, acc[i][3]);
            }
        }
    }

    const float4 b = *reinterpret_cast<const float4*>(&bout[ch + tx * 4]);
    #pragma unroll
    for (int i = 0; i < 4; i++) {
        const int row = r0 + ty * 4 + i;
        const float4 q = *reinterpret_cast<const float4*>(&query[row * CDIM + ch + tx * 4]);
        float4 o = make_float4(acc[i][0] + b.x + q.x, acc[i][1] + b.y + q.y,
                               acc[i][2] + b.z + q.z, acc[i][3] + b.w + q.w);
        *reinterpret_cast<float4*>(&out[row * CDIM + ch + tx * 4]) = o;
    }
}

// ---------------------------------------------------------------------------
// Launch.
// ---------------------------------------------------------------------------
extern "C" void kernel_launch(void* const* d_in, const int* in_sizes, int n_in,
                              void* d_out, int out_size) {
    const float* query = (const float*)d_in[0];
    const float* value = (const float*)d_in[2];
    const float* qpos  = (const float*)d_in[3];
    const float* refp  = (const float*)d_in[4];
    const int*   bmask = (const int*)d_in[5];
    const float* Wv    = (const float*)d_in[8];
    const float* bv    = (const float*)d_in[9];
    const float* Woff  = (const float*)d_in[10];
    const float* boff  = (const float*)d_in[11];
    const float* Wattn = (const float*)d_in[12];
    const float* battn = (const float*)d_in[13];
    const float* Wout  = (const float*)d_in[14];
    const float* bout  = (const float*)d_in[15];
    float* out = (float*)d_out;

    const int smemA = (128 * ACOLS + TM * 128) * sizeof(float);   // 73728
    const int smemH = (128 * 64 + TM * 128) * sizeof(float);      // 65536

    cudaFuncSetAttribute(k_proj_off_attn_t, cudaFuncAttributeMaxDynamicSharedMemorySize, smemA);
    cudaFuncSetAttribute(k_proj_val_t,      cudaFuncAttributeMaxDynamicSharedMemorySize, smemH);
    cudaFuncSetAttribute(k_out_t,           cudaFuncAttributeMaxDynamicSharedMemorySize, smemH);

    // Fork: A on the aux stream, B on the main stream; join before sampling.
    cudaEventRecord(g_aux.evFork, 0);
    cudaStreamWaitEvent(g_aux.s, g_aux.evFork, 0);
    k_proj_off_attn_t<<<(NQ / TM) * 3, 256, smemA, g_aux.s>>>(query, qpos, Woff, boff, Wattn, battn);
    cudaEventRecord(g_aux.evJoin, g_aux.s);

    k_proj_val_t<<<(SCAM * MPIX / TM) * 2, 256, smemH>>>(value, Wv, bv);
    cudaStreamWaitEvent(0, g_aux.evJoin, 0);

    k_sample<<<NQ, CDIM>>>(refp, bmask);
    k_out_t<<<(NQ / TM) * 2, 256, smemH>>>(query, Wout, bout, out);
}